// round 1
// baseline (speedup 1.0000x reference)
#include <cuda_runtime.h>
#include <math.h>

#define LSEQ   4096
#define DMODEL 1024
#define NH     16
#define NKV    4
#define DHEAD  64

// Scratch (no device allocation allowed)
__device__ float g_q[LSEQ * NH * DHEAD];     // 16 MB
__device__ float g_k[LSEQ * NKV * DHEAD];    // 4 MB
__device__ float g_v[LSEQ * NKV * DHEAD];    // 4 MB
__device__ float g_att[LSEQ * NH * DHEAD];   // 16 MB

// ---------------------------------------------------------------------------
// Generic tiled SGEMM: C[M,N] = A[M,K] @ B[K,N], all row-major.
// Requires M,N multiples of 64 and K multiple of 16 (true for all our calls).
// 256 threads, 64x64 block tile, 4x4 per-thread micro-tile, K-step 16.
// ---------------------------------------------------------------------------
__global__ void gemm64(const float* __restrict__ A, const float* __restrict__ B,
                       float* __restrict__ C, int M, int N, int K) {
    __shared__ float As[16][65];   // As[k][m]  (A tile transposed)
    __shared__ float Bs[16][64];   // Bs[k][n]
    const int tid = threadIdx.x;
    const int tx = tid & 15, ty = tid >> 4;
    const int m0 = blockIdx.y << 6, n0 = blockIdx.x << 6;

    float acc[4][4];
#pragma unroll
    for (int i = 0; i < 4; i++)
#pragma unroll
        for (int j = 0; j < 4; j++) acc[i][j] = 0.f;

    for (int k0 = 0; k0 < K; k0 += 16) {
        // A tile: 64 rows x 16 cols -> As[k][m]
        {
            int r = tid >> 2, c4 = (tid & 3) << 2;
            float4 av = *(const float4*)(A + (size_t)(m0 + r) * K + k0 + c4);
            As[c4 + 0][r] = av.x;
            As[c4 + 1][r] = av.y;
            As[c4 + 2][r] = av.z;
            As[c4 + 3][r] = av.w;
        }
        // B tile: 16 rows x 64 cols
        {
            int br = tid >> 4, bc = (tid & 15) << 2;
            *(float4*)(&Bs[br][bc]) = *(const float4*)(B + (size_t)(k0 + br) * N + n0 + bc);
        }
        __syncthreads();

#pragma unroll
        for (int k = 0; k < 16; k++) {
            float a[4], b[4];
#pragma unroll
            for (int i = 0; i < 4; i++) a[i] = As[k][ty * 4 + i];
            float4 bv = *(const float4*)(&Bs[k][tx * 4]);
            b[0] = bv.x; b[1] = bv.y; b[2] = bv.z; b[3] = bv.w;
#pragma unroll
            for (int i = 0; i < 4; i++)
#pragma unroll
                for (int j = 0; j < 4; j++) acc[i][j] += a[i] * b[j];
        }
        __syncthreads();
    }

#pragma unroll
    for (int i = 0; i < 4; i++) {
        float4 o = make_float4(acc[i][0], acc[i][1], acc[i][2], acc[i][3]);
        *(float4*)(C + (size_t)(m0 + ty * 4 + i) * N + n0 + tx * 4) = o;
    }
}

// ---------------------------------------------------------------------------
// RoPE in-place on buf[L][nheads][64].
// out[i]    = x[i]*cos(a_i) - x[i+32]*sin(a_i)
// out[i+32] = x[i+32]*cos(a_i) + x[i]*sin(a_i),  a_i = pos * 10000^(-i/32)
// ---------------------------------------------------------------------------
__global__ void rope(float* __restrict__ buf, int nheads) {
    int idx = blockIdx.x * blockDim.x + threadIdx.x;
    int i = idx & 31;
    int th = idx >> 5;               // pos * nheads + h
    if (th >= LSEQ * nheads) return;
    int pos = th / nheads;
    float inv = powf(10000.0f, -(float)i * (1.0f / 32.0f));
    float ang = (float)pos * inv;
    float s, c;
    sincosf(ang, &s, &c);
    float* p = buf + (size_t)th * DHEAD;
    float x1 = p[i], x2 = p[i + 32];
    p[i]      = x1 * c - x2 * s;
    p[i + 32] = x2 * c + x1 * s;
}

// ---------------------------------------------------------------------------
// Flash-attention (non-causal, full softmax over 4096 keys).
// grid = (L/64, NH), 256 threads. 64 query rows per block, 64-key tiles.
// Thread (ty,tx) [16x16] owns S/O 4x4 micro-tile: rows ty*4+i, cols tx*4+j.
// Row statistics (m, l) shared across the 16 tx-lanes of a row via shfl.
// ---------------------------------------------------------------------------
#define ATT_SMEM_FLOATS (3 * 64 * 65 + 64 * 64)
__global__ void attn_kernel() {
    extern __shared__ float sm[];
    float (*Qs)[65] = (float(*)[65])(sm);                 // Qs[d][r] (scaled)
    float (*Ks)[65] = (float(*)[65])(sm + 64 * 65);       // Ks[d][s]
    float (*Ps)[65] = (float(*)[65])(sm + 2 * 64 * 65);   // Ps[s][r]
    float (*Vs)[64] = (float(*)[64])(sm + 3 * 64 * 65);   // Vs[s][d]

    const int h = blockIdx.y, kvh = h >> 2;
    const int q0 = blockIdx.x << 6;
    const int tid = threadIdx.x;
    const int tx = tid & 15, ty = tid >> 4;
    const float scale = 0.125f;   // DH^-0.5

    for (int e = tid; e < 4096; e += 256) {
        int r = e >> 6, d = e & 63;
        Qs[d][r] = g_q[(size_t)(q0 + r) * (NH * DHEAD) + h * DHEAD + d] * scale;
    }

    float m[4], l[4], O[4][4];
#pragma unroll
    for (int i = 0; i < 4; i++) {
        m[i] = -1e30f; l[i] = 0.f;
#pragma unroll
        for (int j = 0; j < 4; j++) O[i][j] = 0.f;
    }
    __syncthreads();

    for (int s0 = 0; s0 < LSEQ; s0 += 64) {
        for (int e = tid; e < 4096; e += 256) {
            int s = e >> 6, d = e & 63;
            size_t g = (size_t)(s0 + s) * (NKV * DHEAD) + kvh * DHEAD + d;
            Ks[d][s] = g_k[g];
            Vs[s][d] = g_v[g];
        }
        __syncthreads();

        // S = (scaled Q) @ K^T, 4x4 per thread
        float Sv[4][4];
#pragma unroll
        for (int i = 0; i < 4; i++)
#pragma unroll
            for (int j = 0; j < 4; j++) Sv[i][j] = 0.f;

#pragma unroll 8
        for (int d = 0; d < 64; d++) {
            float a[4], b[4];
#pragma unroll
            for (int i = 0; i < 4; i++) a[i] = Qs[d][ty * 4 + i];
#pragma unroll
            for (int j = 0; j < 4; j++) b[j] = Ks[d][tx * 4 + j];
#pragma unroll
            for (int i = 0; i < 4; i++)
#pragma unroll
                for (int j = 0; j < 4; j++) Sv[i][j] += a[i] * b[j];
        }

        // online softmax update
#pragma unroll
        for (int i = 0; i < 4; i++) {
            float mt = fmaxf(fmaxf(Sv[i][0], Sv[i][1]), fmaxf(Sv[i][2], Sv[i][3]));
            mt = fmaxf(mt, __shfl_xor_sync(0xffffffffu, mt, 1));
            mt = fmaxf(mt, __shfl_xor_sync(0xffffffffu, mt, 2));
            mt = fmaxf(mt, __shfl_xor_sync(0xffffffffu, mt, 4));
            mt = fmaxf(mt, __shfl_xor_sync(0xffffffffu, mt, 8));
            float mn = fmaxf(m[i], mt);
            float al = __expf(m[i] - mn);
            m[i] = mn;
            float rs = 0.f;
#pragma unroll
            for (int j = 0; j < 4; j++) {
                float p = __expf(Sv[i][j] - mn);
                Ps[tx * 4 + j][ty * 4 + i] = p;
                rs += p;
            }
            l[i] = l[i] * al + rs;
#pragma unroll
            for (int j = 0; j < 4; j++) O[i][j] *= al;
        }
        __syncthreads();

        // O += P @ V
#pragma unroll 8
        for (int s = 0; s < 64; s++) {
            float a[4];
#pragma unroll
            for (int i = 0; i < 4; i++) a[i] = Ps[s][ty * 4 + i];
            float4 v = *(const float4*)(&Vs[s][tx * 4]);
            float b[4] = {v.x, v.y, v.z, v.w};
#pragma unroll
            for (int i = 0; i < 4; i++)
#pragma unroll
                for (int j = 0; j < 4; j++) O[i][j] += a[i] * b[j];
        }
        __syncthreads();
    }

#pragma unroll
    for (int i = 0; i < 4; i++) {
        l[i] += __shfl_xor_sync(0xffffffffu, l[i], 1);
        l[i] += __shfl_xor_sync(0xffffffffu, l[i], 2);
        l[i] += __shfl_xor_sync(0xffffffffu, l[i], 4);
        l[i] += __shfl_xor_sync(0xffffffffu, l[i], 8);
        float inv = 1.0f / l[i];
        float4 o = make_float4(O[i][0] * inv, O[i][1] * inv, O[i][2] * inv, O[i][3] * inv);
        *(float4*)(g_att + (size_t)(q0 + ty * 4 + i) * (NH * DHEAD) + h * DHEAD + tx * 4) = o;
    }
}

// ---------------------------------------------------------------------------
extern "C" void kernel_launch(void* const* d_in, const int* in_sizes, int n_in,
                              void* d_out, int out_size) {
    const float* x  = (const float*)d_in[0];
    const float* Wq = (const float*)d_in[1];
    const float* Wk = (const float*)d_in[2];
    const float* Wv = (const float*)d_in[3];
    const float* Wo = (const float*)d_in[4];
    float* out = (float*)d_out;

    float *qp, *kp, *vp, *ap;
    cudaGetSymbolAddress((void**)&qp, g_q);
    cudaGetSymbolAddress((void**)&kp, g_k);
    cudaGetSymbolAddress((void**)&vp, g_v);
    cudaGetSymbolAddress((void**)&ap, g_att);

    const int att_smem = ATT_SMEM_FLOATS * (int)sizeof(float);
    cudaFuncSetAttribute(attn_kernel, cudaFuncAttributeMaxDynamicSharedMemorySize, att_smem);

    // Projections
    gemm64<<<dim3(DMODEL / 64, LSEQ / 64), 256>>>(x, Wq, qp, LSEQ, NH * DHEAD, DMODEL);
    gemm64<<<dim3((NKV * DHEAD) / 64, LSEQ / 64), 256>>>(x, Wk, kp, LSEQ, NKV * DHEAD, DMODEL);
    gemm64<<<dim3((NKV * DHEAD) / 64, LSEQ / 64), 256>>>(x, Wv, vp, LSEQ, NKV * DHEAD, DMODEL);

    // RoPE on q and k
    rope<<<(LSEQ * NH * 32 + 255) / 256, 256>>>(qp, NH);
    rope<<<(LSEQ * NKV * 32 + 255) / 256, 256>>>(kp, NKV);

    // Attention
    attn_kernel<<<dim3(LSEQ / 64, NH), 256, att_smem>>>();

    // Output projection
    gemm64<<<dim3(DMODEL / 64, LSEQ / 64), 256>>>(ap, Wo, out, LSEQ, DMODEL, DMODEL);
}

// round 2
// speedup vs baseline: 2.7231x; 2.7231x over previous
#include <cuda_runtime.h>
#include <math.h>
#include <stdint.h>

#define LSEQ   4096
#define DMODEL 1024
#define NH     16
#define NKV    4
#define DHEAD  64

// Scratch (no device allocation allowed)
__device__ float g_q[LSEQ * NH * DHEAD];     // 16 MB
__device__ float g_k[LSEQ * NKV * DHEAD];    // 4 MB
__device__ float g_v[LSEQ * NKV * DHEAD];    // 4 MB
__device__ float g_att[LSEQ * NH * DHEAD];   // 16 MB

__device__ __forceinline__ uint32_t f2tf(float f) {
    uint32_t u;
    asm("cvt.rna.tf32.f32 %0, %1;" : "=r"(u) : "f"(f));
    return u;
}

__device__ __forceinline__ void mma_tf32(float c[4],
                                         uint32_t a0, uint32_t a1, uint32_t a2, uint32_t a3,
                                         uint32_t b0, uint32_t b1) {
    asm volatile(
        "mma.sync.aligned.m16n8k8.row.col.f32.tf32.tf32.f32 "
        "{%0,%1,%2,%3}, {%4,%5,%6,%7}, {%8,%9}, {%0,%1,%2,%3};"
        : "+f"(c[0]), "+f"(c[1]), "+f"(c[2]), "+f"(c[3])
        : "r"(a0), "r"(a1), "r"(a2), "r"(a3), "r"(b0), "r"(b1));
}

// ---------------------------------------------------------------------------
// tf32 tensor-core GEMM: C[M,N] = A[M,K] @ B[K,N], row-major fp32 in/out.
// Block tile 128x128, k-step 32. 256 threads = 8 warps in 4(m) x 2(n) grid;
// warp tile 32x64 = 2 m-frags x 8 n-frags of m16n8k8.
// Requires M%128==0, N%128==0, K%32==0 (true for all calls here).
// ---------------------------------------------------------------------------
__global__ void gemm_tf32(const float* __restrict__ A, const float* __restrict__ B,
                          float* __restrict__ C, int M, int N, int K) {
    __shared__ uint32_t As[128][36];   // [m][k], tf32 bits
    __shared__ uint32_t Bs[32][132];   // [k][n], tf32 bits

    const int tid  = threadIdx.x;
    const int lane = tid & 31;
    const int warp = tid >> 5;
    const int g = lane >> 2, t = lane & 3;
    const int wm = (warp >> 1) << 5;   // 0,32,64,96
    const int wn = (warp & 1) << 6;    // 0,64
    const int m0 = blockIdx.y << 7, n0 = blockIdx.x << 7;

    float acc[2][8][4];
#pragma unroll
    for (int i = 0; i < 2; i++)
#pragma unroll
        for (int j = 0; j < 8; j++)
#pragma unroll
            for (int q = 0; q < 4; q++) acc[i][j][q] = 0.f;

    for (int k0 = 0; k0 < K; k0 += 32) {
        // A tile: 128 x 32
#pragma unroll
        for (int i = 0; i < 4; i++) {
            int lin = i * 256 + tid;
            int r = lin >> 3, c4 = (lin & 7) << 2;
            float4 v = *(const float4*)(A + (size_t)(m0 + r) * K + k0 + c4);
            uint4 u = make_uint4(f2tf(v.x), f2tf(v.y), f2tf(v.z), f2tf(v.w));
            *(uint4*)&As[r][c4] = u;
        }
        // B tile: 32 x 128
#pragma unroll
        for (int i = 0; i < 4; i++) {
            int lin = i * 256 + tid;
            int r = lin >> 5, c4 = (lin & 31) << 2;
            float4 v = *(const float4*)(B + (size_t)(k0 + r) * N + n0 + c4);
            uint4 u = make_uint4(f2tf(v.x), f2tf(v.y), f2tf(v.z), f2tf(v.w));
            *(uint4*)&Bs[r][c4] = u;
        }
        __syncthreads();

#pragma unroll
        for (int kc = 0; kc < 4; kc++) {
            uint32_t a[2][4];
#pragma unroll
            for (int mt = 0; mt < 2; mt++) {
                int rb = wm + mt * 16 + g;
                a[mt][0] = As[rb][kc * 8 + t];
                a[mt][1] = As[rb + 8][kc * 8 + t];
                a[mt][2] = As[rb][kc * 8 + t + 4];
                a[mt][3] = As[rb + 8][kc * 8 + t + 4];
            }
#pragma unroll
            for (int nt = 0; nt < 8; nt++) {
                uint32_t b0 = Bs[kc * 8 + t][wn + nt * 8 + g];
                uint32_t b1 = Bs[kc * 8 + t + 4][wn + nt * 8 + g];
                mma_tf32(acc[0][nt], a[0][0], a[0][1], a[0][2], a[0][3], b0, b1);
                mma_tf32(acc[1][nt], a[1][0], a[1][1], a[1][2], a[1][3], b0, b1);
            }
        }
        __syncthreads();
    }

#pragma unroll
    for (int mt = 0; mt < 2; mt++)
#pragma unroll
        for (int nt = 0; nt < 8; nt++) {
            int row = m0 + wm + mt * 16 + g;
            int col = n0 + wn + nt * 8 + 2 * t;
            *(float2*)(C + (size_t)row * N + col)       = make_float2(acc[mt][nt][0], acc[mt][nt][1]);
            *(float2*)(C + (size_t)(row + 8) * N + col) = make_float2(acc[mt][nt][2], acc[mt][nt][3]);
        }
}

// ---------------------------------------------------------------------------
// RoPE in-place on buf[L][nheads][64].
// ---------------------------------------------------------------------------
__global__ void rope(float* __restrict__ buf, int nheads) {
    int idx = blockIdx.x * blockDim.x + threadIdx.x;
    int i = idx & 31;
    int th = idx >> 5;
    if (th >= LSEQ * nheads) return;
    int pos = th / nheads;
    float inv = powf(10000.0f, -(float)i * (1.0f / 32.0f));
    float ang = (float)pos * inv;
    float s, c;
    sincosf(ang, &s, &c);
    float* p = buf + (size_t)th * DHEAD;
    float x1 = p[i], x2 = p[i + 32];
    p[i]      = x1 * c - x2 * s;
    p[i + 32] = x2 * c + x1 * s;
}

// ---------------------------------------------------------------------------
// Flash attention, tf32 tensor cores.
// grid = (L/128, NH), 256 threads = 8 warps. 128 query rows/block, warp w owns
// S/O rows [16w, 16w+16). Key tiles of 64. K and V both staged as [s][d].
// Ps (exp(S-m)) staged per-warp in SMEM for the P@V A-fragments.
// ---------------------------------------------------------------------------
#define ATT_SMEM_BYTES ((128 + 64 + 64 + 128) * 68 * 4)
__global__ void attn_tf32() {
    extern __shared__ uint32_t sm[];
    uint32_t (*Qs)[68] = (uint32_t(*)[68])(sm);                      // [q][d]
    uint32_t (*Ks)[68] = (uint32_t(*)[68])(sm + 128 * 68);           // [s][d]
    uint32_t (*Vs)[68] = (uint32_t(*)[68])(sm + (128 + 64) * 68);    // [s][d]
    uint32_t (*Ps)[68] = (uint32_t(*)[68])(sm + (128 + 128) * 68);   // [q][s]

    const int h = blockIdx.y, kvh = h >> 2;
    const int q0 = blockIdx.x << 7;
    const int tid = threadIdx.x;
    const int lane = tid & 31;
    const int warp = tid >> 5;
    const int g = lane >> 2, t = lane & 3;
    const int rb = warp << 4;   // warp's S-row base

    // Load + scale + cvt Q tile (128 x 64)
#pragma unroll
    for (int i = 0; i < 8; i++) {
        int lin = i * 256 + tid;
        int r = lin >> 4, c4 = (lin & 15) << 2;
        float4 v = *(const float4*)(g_q + (size_t)(q0 + r) * (NH * DHEAD) + h * DHEAD + c4);
        uint4 u = make_uint4(f2tf(v.x * 0.125f), f2tf(v.y * 0.125f),
                             f2tf(v.z * 0.125f), f2tf(v.w * 0.125f));
        *(uint4*)&Qs[r][c4] = u;
    }

    float mr0 = -1e30f, mr1 = -1e30f, l0 = 0.f, l1 = 0.f;
    float o[8][4];
#pragma unroll
    for (int nt = 0; nt < 8; nt++)
#pragma unroll
        for (int q = 0; q < 4; q++) o[nt][q] = 0.f;

    __syncthreads();

    for (int s0 = 0; s0 < LSEQ; s0 += 64) {
        // Stage K and V tiles (64 x 64 each), tf32
#pragma unroll
        for (int i = 0; i < 4; i++) {
            int lin = i * 256 + tid;
            int s = lin >> 4, d4 = (lin & 15) << 2;
            size_t gaddr = (size_t)(s0 + s) * (NKV * DHEAD) + kvh * DHEAD + d4;
            float4 kv = *(const float4*)(g_k + gaddr);
            *(uint4*)&Ks[s][d4] = make_uint4(f2tf(kv.x), f2tf(kv.y), f2tf(kv.z), f2tf(kv.w));
            float4 vv = *(const float4*)(g_v + gaddr);
            *(uint4*)&Vs[s][d4] = make_uint4(f2tf(vv.x), f2tf(vv.y), f2tf(vv.z), f2tf(vv.w));
        }
        __syncthreads();

        // S = Qs @ Ks^T  (warp rows rb..rb+15, cols 0..63)
        float sacc[8][4];
#pragma unroll
        for (int nt = 0; nt < 8; nt++)
#pragma unroll
            for (int q = 0; q < 4; q++) sacc[nt][q] = 0.f;

#pragma unroll
        for (int kc = 0; kc < 8; kc++) {
            uint32_t a0 = Qs[rb + g][kc * 8 + t];
            uint32_t a1 = Qs[rb + g + 8][kc * 8 + t];
            uint32_t a2 = Qs[rb + g][kc * 8 + t + 4];
            uint32_t a3 = Qs[rb + g + 8][kc * 8 + t + 4];
#pragma unroll
            for (int nt = 0; nt < 8; nt++) {
                uint32_t b0 = Ks[nt * 8 + g][kc * 8 + t];
                uint32_t b1 = Ks[nt * 8 + g][kc * 8 + t + 4];
                mma_tf32(sacc[nt], a0, a1, a2, a3, b0, b1);
            }
        }

        // Online softmax on fragment rows (g -> row0, g+8 -> row1)
        float mx0 = -1e30f, mx1 = -1e30f;
#pragma unroll
        for (int nt = 0; nt < 8; nt++) {
            mx0 = fmaxf(mx0, fmaxf(sacc[nt][0], sacc[nt][1]));
            mx1 = fmaxf(mx1, fmaxf(sacc[nt][2], sacc[nt][3]));
        }
        mx0 = fmaxf(mx0, __shfl_xor_sync(0xffffffffu, mx0, 1));
        mx0 = fmaxf(mx0, __shfl_xor_sync(0xffffffffu, mx0, 2));
        mx1 = fmaxf(mx1, __shfl_xor_sync(0xffffffffu, mx1, 1));
        mx1 = fmaxf(mx1, __shfl_xor_sync(0xffffffffu, mx1, 2));

        float mn0 = fmaxf(mr0, mx0), mn1 = fmaxf(mr1, mx1);
        float al0 = __expf(mr0 - mn0), al1 = __expf(mr1 - mn1);
        mr0 = mn0; mr1 = mn1;

        float rs0 = 0.f, rs1 = 0.f;
#pragma unroll
        for (int nt = 0; nt < 8; nt++) {
            float p0 = __expf(sacc[nt][0] - mn0);
            float p1 = __expf(sacc[nt][1] - mn0);
            float p2 = __expf(sacc[nt][2] - mn1);
            float p3 = __expf(sacc[nt][3] - mn1);
            rs0 += p0 + p1; rs1 += p2 + p3;
            int col = nt * 8 + 2 * t;
            *(uint2*)&Ps[rb + g][col]     = make_uint2(f2tf(p0), f2tf(p1));
            *(uint2*)&Ps[rb + g + 8][col] = make_uint2(f2tf(p2), f2tf(p3));
        }
        rs0 += __shfl_xor_sync(0xffffffffu, rs0, 1);
        rs0 += __shfl_xor_sync(0xffffffffu, rs0, 2);
        rs1 += __shfl_xor_sync(0xffffffffu, rs1, 1);
        rs1 += __shfl_xor_sync(0xffffffffu, rs1, 2);
        l0 = l0 * al0 + rs0;
        l1 = l1 * al1 + rs1;

#pragma unroll
        for (int nt = 0; nt < 8; nt++) {
            o[nt][0] *= al0; o[nt][1] *= al0;
            o[nt][2] *= al1; o[nt][3] *= al1;
        }
        __syncwarp();

        // O += P @ V   (k-dim = s, 8 chunks)
#pragma unroll
        for (int kc = 0; kc < 8; kc++) {
            uint32_t a0 = Ps[rb + g][kc * 8 + t];
            uint32_t a1 = Ps[rb + g + 8][kc * 8 + t];
            uint32_t a2 = Ps[rb + g][kc * 8 + t + 4];
            uint32_t a3 = Ps[rb + g + 8][kc * 8 + t + 4];
#pragma unroll
            for (int nt = 0; nt < 8; nt++) {
                uint32_t b0 = Vs[kc * 8 + t][nt * 8 + g];
                uint32_t b1 = Vs[kc * 8 + t + 4][nt * 8 + g];
                mma_tf32(o[nt], a0, a1, a2, a3, b0, b1);
            }
        }
        __syncthreads();
    }

    float inv0 = 1.0f / l0, inv1 = 1.0f / l1;
#pragma unroll
    for (int nt = 0; nt < 8; nt++) {
        int col = h * DHEAD + nt * 8 + 2 * t;
        int row = q0 + rb + g;
        *(float2*)(g_att + (size_t)row * (NH * DHEAD) + col) =
            make_float2(o[nt][0] * inv0, o[nt][1] * inv0);
        *(float2*)(g_att + (size_t)(row + 8) * (NH * DHEAD) + col) =
            make_float2(o[nt][2] * inv1, o[nt][3] * inv1);
    }
}

// ---------------------------------------------------------------------------
extern "C" void kernel_launch(void* const* d_in, const int* in_sizes, int n_in,
                              void* d_out, int out_size) {
    const float* x  = (const float*)d_in[0];
    const float* Wq = (const float*)d_in[1];
    const float* Wk = (const float*)d_in[2];
    const float* Wv = (const float*)d_in[3];
    const float* Wo = (const float*)d_in[4];
    float* out = (float*)d_out;

    float *qp, *kp, *vp, *ap;
    cudaGetSymbolAddress((void**)&qp, g_q);
    cudaGetSymbolAddress((void**)&kp, g_k);
    cudaGetSymbolAddress((void**)&vp, g_v);
    cudaGetSymbolAddress((void**)&ap, g_att);

    cudaFuncSetAttribute(attn_tf32, cudaFuncAttributeMaxDynamicSharedMemorySize, ATT_SMEM_BYTES);

    // Projections (tf32 tensor cores)
    gemm_tf32<<<dim3((NH * DHEAD) / 128, LSEQ / 128), 256>>>(x, Wq, qp, LSEQ, NH * DHEAD, DMODEL);
    gemm_tf32<<<dim3((NKV * DHEAD) / 128, LSEQ / 128), 256>>>(x, Wk, kp, LSEQ, NKV * DHEAD, DMODEL);
    gemm_tf32<<<dim3((NKV * DHEAD) / 128, LSEQ / 128), 256>>>(x, Wv, vp, LSEQ, NKV * DHEAD, DMODEL);

    // RoPE
    rope<<<(LSEQ * NH * 32 + 255) / 256, 256>>>(qp, NH);
    rope<<<(LSEQ * NKV * 32 + 255) / 256, 256>>>(kp, NKV);

    // Attention
    attn_tf32<<<dim3(LSEQ / 128, NH), 256, ATT_SMEM_BYTES>>>();

    // Output projection
    gemm_tf32<<<dim3(DMODEL / 128, LSEQ / 128), 256>>>(ap, Wo, out, LSEQ, DMODEL, DMODEL);
}

// round 4
// speedup vs baseline: 3.1922x; 1.1722x over previous
#include <cuda_runtime.h>
#include <math.h>
#include <stdint.h>

#define LSEQ   4096
#define DMODEL 1024
#define NH     16
#define NKV    4
#define DHEAD  64

// Scratch (no device allocation allowed)
__device__ float g_q[LSEQ * NH * DHEAD];     // 16 MB
__device__ float g_k[LSEQ * NKV * DHEAD];    // 4 MB
__device__ float g_v[LSEQ * NKV * DHEAD];    // 4 MB
__device__ float g_att[LSEQ * NH * DHEAD];   // 16 MB

__device__ __forceinline__ uint32_t f2tf(float f) {
    uint32_t u;
    asm("cvt.rna.tf32.f32 %0, %1;" : "=r"(u) : "f"(f));
    return u;
}

__device__ __forceinline__ void mma_tf32(float c[4],
                                         uint32_t a0, uint32_t a1, uint32_t a2, uint32_t a3,
                                         uint32_t b0, uint32_t b1) {
    asm volatile(
        "mma.sync.aligned.m16n8k8.row.col.f32.tf32.tf32.f32 "
        "{%0,%1,%2,%3}, {%4,%5,%6,%7}, {%8,%9}, {%0,%1,%2,%3};"
        : "+f"(c[0]), "+f"(c[1]), "+f"(c[2]), "+f"(c[3])
        : "r"(a0), "r"(a1), "r"(a2), "r"(a3), "r"(b0), "r"(b1));
}

// ---------------------------------------------------------------------------
// Pipelined tf32 GEMM body: C[.,N] = A[.,K] @ B[K,N], row-major fp32.
// 128x128 block tile, k-step 32, double-buffered SMEM, reg-staged prefetch,
// one __syncthreads per k-step. 256 threads = 8 warps (4m x 2n), warp 32x64.
// ---------------------------------------------------------------------------
#define GEMM_SMEM_BYTES ((2 * 128 * 36 + 2 * 32 * 132) * 4)
#define AS(b, r, c) dsm[(b) * 4608 + (r) * 36 + (c)]
#define BS(b, r, c) dsm[9216 + (b) * 4224 + (r) * 132 + (c)]

__device__ __forceinline__ void gemm_body(const float* __restrict__ A,
                                          const float* __restrict__ B,
                                          float* __restrict__ C,
                                          int N, int K, int m0, int n0) {
    extern __shared__ uint32_t dsm[];
    const int tid  = threadIdx.x;
    const int lane = tid & 31;
    const int warp = tid >> 5;
    const int g = lane >> 2, t = lane & 3;
    const int wm = (warp >> 1) << 5;
    const int wn = (warp & 1) << 6;

    const int ar_r = tid >> 3, ar_c = (tid & 7) << 2;    // A tile: 128x32
    const int br_r = tid >> 5, br_c = (tid & 31) << 2;   // B tile: 32x128

    float4 ar[4], br[4];
#pragma unroll
    for (int i = 0; i < 4; i++) {
        ar[i] = *(const float4*)(A + (size_t)(m0 + ar_r + i * 32) * K + ar_c);
        br[i] = *(const float4*)(B + (size_t)(br_r + i * 8) * N + n0 + br_c);
    }
#pragma unroll
    for (int i = 0; i < 4; i++) {
        *(uint4*)&AS(0, ar_r + i * 32, ar_c) =
            make_uint4(f2tf(ar[i].x), f2tf(ar[i].y), f2tf(ar[i].z), f2tf(ar[i].w));
        *(uint4*)&BS(0, br_r + i * 8, br_c) =
            make_uint4(f2tf(br[i].x), f2tf(br[i].y), f2tf(br[i].z), f2tf(br[i].w));
    }
    __syncthreads();

    float acc[2][8][4];
#pragma unroll
    for (int i = 0; i < 2; i++)
#pragma unroll
        for (int j = 0; j < 8; j++)
#pragma unroll
            for (int q = 0; q < 4; q++) acc[i][j][q] = 0.f;

    for (int k0 = 0; k0 < K; k0 += 32) {
        const int cur = (k0 >> 5) & 1;
        const bool more = (k0 + 32 < K);
        if (more) {
#pragma unroll
            for (int i = 0; i < 4; i++) {
                ar[i] = *(const float4*)(A + (size_t)(m0 + ar_r + i * 32) * K + k0 + 32 + ar_c);
                br[i] = *(const float4*)(B + (size_t)(k0 + 32 + br_r + i * 8) * N + n0 + br_c);
            }
        }
#pragma unroll
        for (int kc = 0; kc < 4; kc++) {
            uint32_t a[2][4];
#pragma unroll
            for (int mt = 0; mt < 2; mt++) {
                int rbm = wm + mt * 16 + g;
                a[mt][0] = AS(cur, rbm, kc * 8 + t);
                a[mt][1] = AS(cur, rbm + 8, kc * 8 + t);
                a[mt][2] = AS(cur, rbm, kc * 8 + t + 4);
                a[mt][3] = AS(cur, rbm + 8, kc * 8 + t + 4);
            }
#pragma unroll
            for (int nt = 0; nt < 8; nt++) {
                uint32_t b0 = BS(cur, kc * 8 + t, wn + nt * 8 + g);
                uint32_t b1 = BS(cur, kc * 8 + t + 4, wn + nt * 8 + g);
                mma_tf32(acc[0][nt], a[0][0], a[0][1], a[0][2], a[0][3], b0, b1);
                mma_tf32(acc[1][nt], a[1][0], a[1][1], a[1][2], a[1][3], b0, b1);
            }
        }
        if (more) {
#pragma unroll
            for (int i = 0; i < 4; i++) {
                *(uint4*)&AS(cur ^ 1, ar_r + i * 32, ar_c) =
                    make_uint4(f2tf(ar[i].x), f2tf(ar[i].y), f2tf(ar[i].z), f2tf(ar[i].w));
                *(uint4*)&BS(cur ^ 1, br_r + i * 8, br_c) =
                    make_uint4(f2tf(br[i].x), f2tf(br[i].y), f2tf(br[i].z), f2tf(br[i].w));
            }
        }
        __syncthreads();
    }

#pragma unroll
    for (int mt = 0; mt < 2; mt++)
#pragma unroll
        for (int nt = 0; nt < 8; nt++) {
            int row = m0 + wm + mt * 16 + g;
            int col = n0 + wn + nt * 8 + 2 * t;
            *(float2*)(C + (size_t)row * N + col)       = make_float2(acc[mt][nt][0], acc[mt][nt][1]);
            *(float2*)(C + (size_t)(row + 8) * N + col) = make_float2(acc[mt][nt][2], acc[mt][nt][3]);
        }
}

// Fused Q/K/V projection: grid.x = 12 n-blocks (8 Q, 2 K, 2 V), grid.y = 32 m-blocks.
__global__ __launch_bounds__(256, 2) void qkv_gemm(const float* __restrict__ x,
                                                   const float* __restrict__ Wq,
                                                   const float* __restrict__ Wk,
                                                   const float* __restrict__ Wv) {
    const int bx = blockIdx.x;
    const float* B; float* C; int N, nb;
    if (bx < 8)       { B = Wq; C = g_q; N = 1024; nb = bx; }
    else if (bx < 10) { B = Wk; C = g_k; N = 256;  nb = bx - 8; }
    else              { B = Wv; C = g_v; N = 256;  nb = bx - 10; }
    gemm_body(x, B, C, N, DMODEL, blockIdx.y << 7, nb << 7);
}

__global__ __launch_bounds__(256, 2) void oproj_gemm(const float* __restrict__ Wo,
                                                     float* __restrict__ out) {
    gemm_body(g_att, Wo, out, DMODEL, DMODEL, blockIdx.y << 7, blockIdx.x << 7);
}

// ---------------------------------------------------------------------------
// RoPE in-place on buf[L][nheads][64].
// ---------------------------------------------------------------------------
__global__ void rope(float* __restrict__ buf, int nheads) {
    int idx = blockIdx.x * blockDim.x + threadIdx.x;
    int i = idx & 31;
    int th = idx >> 5;
    if (th >= LSEQ * nheads) return;
    int pos = th / nheads;
    float inv = powf(10000.0f, -(float)i * (1.0f / 32.0f));
    float ang = (float)pos * inv;
    float s, c;
    sincosf(ang, &s, &c);
    float* p = buf + (size_t)th * DHEAD;
    float x1 = p[i], x2 = p[i + 32];
    p[i]      = x1 * c - x2 * s;
    p[i + 32] = x2 * c + x1 * s;
}

// ---------------------------------------------------------------------------
// Flash attention, tf32 mma, P-fragments via shuffle relayout (no P SMEM).
// grid = (32, 16), 256 threads = 8 warps, warp w owns S/O rows [16w,16w+16).
// SMEM: Q[128][68] + K[64][68] + V[64][68] = 69.6 KB -> 2 CTAs/SM.
// K/V prefetched into registers one 64-key tile ahead.
// ---------------------------------------------------------------------------
#define ATT_SMEM_BYTES ((128 + 64 + 64) * 68 * 4)
#define QS(r, c) smatt[(r) * 68 + (c)]
#define KS(r, c) smatt[128 * 68 + (r) * 68 + (c)]
#define VS(r, c) smatt[192 * 68 + (r) * 68 + (c)]

__global__ __launch_bounds__(256, 2) void attn_tf32() {
    extern __shared__ uint32_t smatt[];
    const int h = blockIdx.y, kvh = h >> 2;
    const int q0 = blockIdx.x << 7;
    const int tid = threadIdx.x;
    const int lane = tid & 31;
    const int warp = tid >> 5;
    const int g = lane >> 2, t = lane & 3;
    const int rb = warp << 4;
    const int lb = lane & ~3;           // 4g: base lane of this row-group
    const int srcA = lb | (t >> 1);
    const int srcB = srcA + 2;
    const bool odd = (t & 1);

    // Stage Q (scaled by DH^-0.5)
#pragma unroll
    for (int i = 0; i < 8; i++) {
        int lin = i * 256 + tid;
        int r = lin >> 4, c4 = (lin & 15) << 2;
        float4 v = *(const float4*)(g_q + (size_t)(q0 + r) * (NH * DHEAD) + h * DHEAD + c4);
        *(uint4*)&QS(r, c4) = make_uint4(f2tf(v.x * 0.125f), f2tf(v.y * 0.125f),
                                         f2tf(v.z * 0.125f), f2tf(v.w * 0.125f));
    }

    // Prefetch K/V tile 0
    const int kv_s = tid >> 4;
    const int kv_d = (tid & 15) << 2;
    float4 kr[4], vr[4];
#pragma unroll
    for (int i = 0; i < 4; i++) {
        size_t ga = (size_t)(i * 16 + kv_s) * (NKV * DHEAD) + kvh * DHEAD + kv_d;
        kr[i] = *(const float4*)(g_k + ga);
        vr[i] = *(const float4*)(g_v + ga);
    }

    float mr0 = -1e30f, mr1 = -1e30f, l0 = 0.f, l1 = 0.f;
    float o[8][4];
#pragma unroll
    for (int nt = 0; nt < 8; nt++)
#pragma unroll
        for (int q = 0; q < 4; q++) o[nt][q] = 0.f;

    for (int it = 0; it < 64; it++) {
        __syncthreads();   // previous tile's compute done (it=0: Q staged)
#pragma unroll
        for (int i = 0; i < 4; i++) {
            int s = i * 16 + kv_s;
            *(uint4*)&KS(s, kv_d) = make_uint4(f2tf(kr[i].x), f2tf(kr[i].y),
                                               f2tf(kr[i].z), f2tf(kr[i].w));
            *(uint4*)&VS(s, kv_d) = make_uint4(f2tf(vr[i].x), f2tf(vr[i].y),
                                               f2tf(vr[i].z), f2tf(vr[i].w));
        }
        __syncthreads();   // tile ready

        if (it + 1 < 64) {   // prefetch next tile (overlaps compute)
#pragma unroll
            for (int i = 0; i < 4; i++) {
                size_t ga = (size_t)((it + 1) * 64 + i * 16 + kv_s) * (NKV * DHEAD)
                            + kvh * DHEAD + kv_d;
                kr[i] = *(const float4*)(g_k + ga);
                vr[i] = *(const float4*)(g_v + ga);
            }
        }

        // S = Q @ K^T
        float sacc[8][4];
#pragma unroll
        for (int nt = 0; nt < 8; nt++)
#pragma unroll
            for (int q = 0; q < 4; q++) sacc[nt][q] = 0.f;

#pragma unroll
        for (int kc = 0; kc < 8; kc++) {
            uint32_t a0 = QS(rb + g, kc * 8 + t);
            uint32_t a1 = QS(rb + g + 8, kc * 8 + t);
            uint32_t a2 = QS(rb + g, kc * 8 + t + 4);
            uint32_t a3 = QS(rb + g + 8, kc * 8 + t + 4);
#pragma unroll
            for (int nt = 0; nt < 8; nt++) {
                uint32_t b0 = KS(nt * 8 + g, kc * 8 + t);
                uint32_t b1 = KS(nt * 8 + g, kc * 8 + t + 4);
                mma_tf32(sacc[nt], a0, a1, a2, a3, b0, b1);
            }
        }

        // Online softmax; overwrite sacc with tf32 bits of exp(S - m)
        float mx0 = -1e30f, mx1 = -1e30f;
#pragma unroll
        for (int nt = 0; nt < 8; nt++) {
            mx0 = fmaxf(mx0, fmaxf(sacc[nt][0], sacc[nt][1]));
            mx1 = fmaxf(mx1, fmaxf(sacc[nt][2], sacc[nt][3]));
        }
        mx0 = fmaxf(mx0, __shfl_xor_sync(0xffffffffu, mx0, 1));
        mx0 = fmaxf(mx0, __shfl_xor_sync(0xffffffffu, mx0, 2));
        mx1 = fmaxf(mx1, __shfl_xor_sync(0xffffffffu, mx1, 1));
        mx1 = fmaxf(mx1, __shfl_xor_sync(0xffffffffu, mx1, 2));
        float mn0 = fmaxf(mr0, mx0), mn1 = fmaxf(mr1, mx1);
        float al0 = __expf(mr0 - mn0), al1 = __expf(mr1 - mn1);
        mr0 = mn0; mr1 = mn1;

        float rs0 = 0.f, rs1 = 0.f;
#pragma unroll
        for (int nt = 0; nt < 8; nt++) {
            float p0 = __expf(sacc[nt][0] - mn0);
            float p1 = __expf(sacc[nt][1] - mn0);
            float p2 = __expf(sacc[nt][2] - mn1);
            float p3 = __expf(sacc[nt][3] - mn1);
            rs0 += p0 + p1; rs1 += p2 + p3;
            sacc[nt][0] = __uint_as_float(f2tf(p0));
            sacc[nt][1] = __uint_as_float(f2tf(p1));
            sacc[nt][2] = __uint_as_float(f2tf(p2));
            sacc[nt][3] = __uint_as_float(f2tf(p3));
        }
        rs0 += __shfl_xor_sync(0xffffffffu, rs0, 1);
        rs0 += __shfl_xor_sync(0xffffffffu, rs0, 2);
        rs1 += __shfl_xor_sync(0xffffffffu, rs1, 1);
        rs1 += __shfl_xor_sync(0xffffffffu, rs1, 2);
        l0 = l0 * al0 + rs0;
        l1 = l1 * al1 + rs1;
#pragma unroll
        for (int nt = 0; nt < 8; nt++) {
            o[nt][0] *= al0; o[nt][1] *= al0;
            o[nt][2] *= al1; o[nt][3] *= al1;
        }

        // O += P @ V ; P A-fragments built from sacc C-layout via shuffles
#pragma unroll
        for (int kc = 0; kc < 8; kc++) {
            uint32_t p0 = __float_as_uint(sacc[kc][0]);
            uint32_t p1 = __float_as_uint(sacc[kc][1]);
            uint32_t p2 = __float_as_uint(sacc[kc][2]);
            uint32_t p3 = __float_as_uint(sacc[kc][3]);
            uint32_t sA0 = __shfl_sync(0xffffffffu, p0, srcA);
            uint32_t sA1 = __shfl_sync(0xffffffffu, p1, srcA);
            uint32_t sA2 = __shfl_sync(0xffffffffu, p2, srcA);
            uint32_t sA3 = __shfl_sync(0xffffffffu, p3, srcA);
            uint32_t sB0 = __shfl_sync(0xffffffffu, p0, srcB);
            uint32_t sB1 = __shfl_sync(0xffffffffu, p1, srcB);
            uint32_t sB2 = __shfl_sync(0xffffffffu, p2, srcB);
            uint32_t sB3 = __shfl_sync(0xffffffffu, p3, srcB);
            uint32_t a0 = odd ? sA1 : sA0;
            uint32_t a1 = odd ? sA3 : sA2;
            uint32_t a2 = odd ? sB1 : sB0;
            uint32_t a3 = odd ? sB3 : sB2;
#pragma unroll
            for (int nt = 0; nt < 8; nt++) {
                uint32_t b0 = VS(kc * 8 + t, nt * 8 + g);
                uint32_t b1 = VS(kc * 8 + t + 4, nt * 8 + g);
                mma_tf32(o[nt], a0, a1, a2, a3, b0, b1);
            }
        }
    }

    // l0/l1 already hold the full row sums (quad-reduced every tile).
    float inv0 = 1.0f / l0, inv1 = 1.0f / l1;
#pragma unroll
    for (int nt = 0; nt < 8; nt++) {
        int col = h * DHEAD + nt * 8 + 2 * t;
        int row = q0 + rb + g;
        *(float2*)(g_att + (size_t)row * (NH * DHEAD) + col) =
            make_float2(o[nt][0] * inv0, o[nt][1] * inv0);
        *(float2*)(g_att + (size_t)(row + 8) * (NH * DHEAD) + col) =
            make_float2(o[nt][2] * inv1, o[nt][3] * inv1);
    }
}

// ---------------------------------------------------------------------------
extern "C" void kernel_launch(void* const* d_in, const int* in_sizes, int n_in,
                              void* d_out, int out_size) {
    const float* x  = (const float*)d_in[0];
    const float* Wq = (const float*)d_in[1];
    const float* Wk = (const float*)d_in[2];
    const float* Wv = (const float*)d_in[3];
    const float* Wo = (const float*)d_in[4];
    float* out = (float*)d_out;

    float *qp, *kp;
    cudaGetSymbolAddress((void**)&qp, g_q);
    cudaGetSymbolAddress((void**)&kp, g_k);

    cudaFuncSetAttribute(qkv_gemm,   cudaFuncAttributeMaxDynamicSharedMemorySize, GEMM_SMEM_BYTES);
    cudaFuncSetAttribute(oproj_gemm, cudaFuncAttributeMaxDynamicSharedMemorySize, GEMM_SMEM_BYTES);
    cudaFuncSetAttribute(attn_tf32,  cudaFuncAttributeMaxDynamicSharedMemorySize, ATT_SMEM_BYTES);

    qkv_gemm<<<dim3(12, 32), 256, GEMM_SMEM_BYTES>>>(x, Wq, Wk, Wv);
    rope<<<(LSEQ * NH * 32 + 255) / 256, 256>>>(qp, NH);
    rope<<<(LSEQ * NKV * 32 + 255) / 256, 256>>>(kp, NKV);
    attn_tf32<<<dim3(LSEQ / 128, NH), 256, ATT_SMEM_BYTES>>>();
    oproj_gemm<<<dim3(DMODEL / 128, LSEQ / 128), 256, GEMM_SMEM_BYTES>>>(Wo, out);
}

// round 5
// speedup vs baseline: 3.9557x; 1.2392x over previous
#include <cuda_runtime.h>
#include <math.h>
#include <stdint.h>

#define LSEQ   4096
#define DMODEL 1024
#define NH     16
#define NKV    4
#define DHEAD  64

// Scratch (no device allocation allowed)
__device__ float g_q[LSEQ * NH * DHEAD];     // 16 MB
__device__ float g_k[LSEQ * NKV * DHEAD];    // 4 MB
__device__ float g_v[LSEQ * NKV * DHEAD];    // 4 MB
__device__ float g_att[LSEQ * NH * DHEAD];   // 16 MB

__device__ __forceinline__ uint32_t f2tf(float f) {
    uint32_t u;
    asm("cvt.rna.tf32.f32 %0, %1;" : "=r"(u) : "f"(f));
    return u;
}

__device__ __forceinline__ void mma_tf32(float c[4],
                                         uint32_t a0, uint32_t a1, uint32_t a2, uint32_t a3,
                                         uint32_t b0, uint32_t b1) {
    asm volatile(
        "mma.sync.aligned.m16n8k8.row.col.f32.tf32.tf32.f32 "
        "{%0,%1,%2,%3}, {%4,%5,%6,%7}, {%8,%9}, {%0,%1,%2,%3};"
        : "+f"(c[0]), "+f"(c[1]), "+f"(c[2]), "+f"(c[3])
        : "r"(a0), "r"(a1), "r"(a2), "r"(a3), "r"(b0), "r"(b1));
}

// ---------------------------------------------------------------------------
// Pipelined tf32 GEMM body: C[.,N] = A[.,K] @ B[K,N], row-major fp32.
// 128x128 block tile, k-step 32, double-buffered SMEM, reg-staged prefetch.
// ---------------------------------------------------------------------------
#define GEMM_SMEM_BYTES ((2 * 128 * 36 + 2 * 32 * 132) * 4)
#define AS(b, r, c) dsm[(b) * 4608 + (r) * 36 + (c)]
#define BS(b, r, c) dsm[9216 + (b) * 4224 + (r) * 132 + (c)]

__device__ __forceinline__ void gemm_body(const float* __restrict__ A,
                                          const float* __restrict__ B,
                                          float* __restrict__ C,
                                          int N, int K, int m0, int n0) {
    extern __shared__ uint32_t dsm[];
    const int tid  = threadIdx.x;
    const int lane = tid & 31;
    const int warp = tid >> 5;
    const int g = lane >> 2, t = lane & 3;
    const int wm = (warp >> 1) << 5;
    const int wn = (warp & 1) << 6;

    const int ar_r = tid >> 3, ar_c = (tid & 7) << 2;    // A tile: 128x32
    const int br_r = tid >> 5, br_c = (tid & 31) << 2;   // B tile: 32x128

    float4 ar[4], br[4];
#pragma unroll
    for (int i = 0; i < 4; i++) {
        ar[i] = *(const float4*)(A + (size_t)(m0 + ar_r + i * 32) * K + ar_c);
        br[i] = *(const float4*)(B + (size_t)(br_r + i * 8) * N + n0 + br_c);
    }
#pragma unroll
    for (int i = 0; i < 4; i++) {
        *(uint4*)&AS(0, ar_r + i * 32, ar_c) =
            make_uint4(f2tf(ar[i].x), f2tf(ar[i].y), f2tf(ar[i].z), f2tf(ar[i].w));
        *(uint4*)&BS(0, br_r + i * 8, br_c) =
            make_uint4(f2tf(br[i].x), f2tf(br[i].y), f2tf(br[i].z), f2tf(br[i].w));
    }
    __syncthreads();

    float acc[2][8][4];
#pragma unroll
    for (int i = 0; i < 2; i++)
#pragma unroll
        for (int j = 0; j < 8; j++)
#pragma unroll
            for (int q = 0; q < 4; q++) acc[i][j][q] = 0.f;

    for (int k0 = 0; k0 < K; k0 += 32) {
        const int cur = (k0 >> 5) & 1;
        const bool more = (k0 + 32 < K);
        if (more) {
#pragma unroll
            for (int i = 0; i < 4; i++) {
                ar[i] = *(const float4*)(A + (size_t)(m0 + ar_r + i * 32) * K + k0 + 32 + ar_c);
                br[i] = *(const float4*)(B + (size_t)(k0 + 32 + br_r + i * 8) * N + n0 + br_c);
            }
        }
#pragma unroll
        for (int kc = 0; kc < 4; kc++) {
            uint32_t a[2][4];
#pragma unroll
            for (int mt = 0; mt < 2; mt++) {
                int rbm = wm + mt * 16 + g;
                a[mt][0] = AS(cur, rbm, kc * 8 + t);
                a[mt][1] = AS(cur, rbm + 8, kc * 8 + t);
                a[mt][2] = AS(cur, rbm, kc * 8 + t + 4);
                a[mt][3] = AS(cur, rbm + 8, kc * 8 + t + 4);
            }
#pragma unroll
            for (int nt = 0; nt < 8; nt++) {
                uint32_t b0 = BS(cur, kc * 8 + t, wn + nt * 8 + g);
                uint32_t b1 = BS(cur, kc * 8 + t + 4, wn + nt * 8 + g);
                mma_tf32(acc[0][nt], a[0][0], a[0][1], a[0][2], a[0][3], b0, b1);
                mma_tf32(acc[1][nt], a[1][0], a[1][1], a[1][2], a[1][3], b0, b1);
            }
        }
        if (more) {
#pragma unroll
            for (int i = 0; i < 4; i++) {
                *(uint4*)&AS(cur ^ 1, ar_r + i * 32, ar_c) =
                    make_uint4(f2tf(ar[i].x), f2tf(ar[i].y), f2tf(ar[i].z), f2tf(ar[i].w));
                *(uint4*)&BS(cur ^ 1, br_r + i * 8, br_c) =
                    make_uint4(f2tf(br[i].x), f2tf(br[i].y), f2tf(br[i].z), f2tf(br[i].w));
            }
        }
        __syncthreads();
    }

#pragma unroll
    for (int mt = 0; mt < 2; mt++)
#pragma unroll
        for (int nt = 0; nt < 8; nt++) {
            int row = m0 + wm + mt * 16 + g;
            int col = n0 + wn + nt * 8 + 2 * t;
            *(float2*)(C + (size_t)row * N + col)       = make_float2(acc[mt][nt][0], acc[mt][nt][1]);
            *(float2*)(C + (size_t)(row + 8) * N + col) = make_float2(acc[mt][nt][2], acc[mt][nt][3]);
        }
}

// Fused Q/K/V projection: grid.x = 12 n-blocks (8 Q, 2 K, 2 V), grid.y = 32 m-blocks.
__global__ __launch_bounds__(256, 2) void qkv_gemm(const float* __restrict__ x,
                                                   const float* __restrict__ Wq,
                                                   const float* __restrict__ Wk,
                                                   const float* __restrict__ Wv) {
    const int bx = blockIdx.x;
    const float* B; float* C; int N, nb;
    if (bx < 8)       { B = Wq; C = g_q; N = 1024; nb = bx; }
    else if (bx < 10) { B = Wk; C = g_k; N = 256;  nb = bx - 8; }
    else              { B = Wv; C = g_v; N = 256;  nb = bx - 10; }
    gemm_body(x, B, C, N, DMODEL, blockIdx.y << 7, nb << 7);
}

__global__ __launch_bounds__(256, 2) void oproj_gemm(const float* __restrict__ Wo,
                                                     float* __restrict__ out) {
    gemm_body(g_att, Wo, out, DMODEL, DMODEL, blockIdx.y << 7, blockIdx.x << 7);
}

// ---------------------------------------------------------------------------
// RoPE in-place on buf[L][nheads][64].
// ---------------------------------------------------------------------------
__global__ void rope(float* __restrict__ buf, int nheads) {
    int idx = blockIdx.x * blockDim.x + threadIdx.x;
    int i = idx & 31;
    int th = idx >> 5;
    if (th >= LSEQ * nheads) return;
    int pos = th / nheads;
    float inv = powf(10000.0f, -(float)i * (1.0f / 32.0f));
    float ang = (float)pos * inv;
    float s, c;
    sincosf(ang, &s, &c);
    float* p = buf + (size_t)th * DHEAD;
    float x1 = p[i], x2 = p[i + 32];
    p[i]      = x1 * c - x2 * s;
    p[i + 32] = x2 * c + x1 * s;
}

// ---------------------------------------------------------------------------
// Flash attention v2: tf32 mma, 256 q-rows/CTA, 8 warps, warp = 32 rows
// (2 x 16-row m-frags) so every K/V b-fragment feeds 2 MMAs.
// grid = (16, 16). SMEM: Q[256][68] + K[64][68] + V[64][68] = 104.4 KB.
// K/V prefetched into registers one 64-key tile ahead. P via shuffle relayout.
// ---------------------------------------------------------------------------
#define ATT_SMEM_BYTES ((256 + 64 + 64) * 68 * 4)
#define QS(r, c) smatt[(r) * 68 + (c)]
#define KS(r, c) smatt[256 * 68 + (r) * 68 + (c)]
#define VS(r, c) smatt[320 * 68 + (r) * 68 + (c)]

__global__ __launch_bounds__(256, 1) void attn_tf32() {
    extern __shared__ uint32_t smatt[];
    const int h = blockIdx.y, kvh = h >> 2;
    const int q0 = blockIdx.x << 8;
    const int tid = threadIdx.x;
    const int lane = tid & 31;
    const int warp = tid >> 5;
    const int g = lane >> 2, t = lane & 3;
    const int rw = warp << 5;           // warp's 32-row base
    const int lb = lane & ~3;
    const int srcA = lb | (t >> 1);
    const int srcB = srcA + 2;
    const bool odd = (t & 1);

    // Stage Q (scaled by DH^-0.5): 256 x 64
#pragma unroll
    for (int i = 0; i < 16; i++) {
        int lin = i * 256 + tid;
        int r = lin >> 4, c4 = (lin & 15) << 2;
        float4 v = *(const float4*)(g_q + (size_t)(q0 + r) * (NH * DHEAD) + h * DHEAD + c4);
        *(uint4*)&QS(r, c4) = make_uint4(f2tf(v.x * 0.125f), f2tf(v.y * 0.125f),
                                         f2tf(v.z * 0.125f), f2tf(v.w * 0.125f));
    }

    // Prefetch K/V tile 0
    const int kv_s = tid >> 4;
    const int kv_d = (tid & 15) << 2;
    float4 kr[4], vr[4];
#pragma unroll
    for (int i = 0; i < 4; i++) {
        size_t ga = (size_t)(i * 16 + kv_s) * (NKV * DHEAD) + kvh * DHEAD + kv_d;
        kr[i] = *(const float4*)(g_k + ga);
        vr[i] = *(const float4*)(g_v + ga);
    }

    float mr[2][2], l[2][2];
    float o[2][8][4];
#pragma unroll
    for (int mf = 0; mf < 2; mf++) {
        mr[mf][0] = mr[mf][1] = -1e30f;
        l[mf][0] = l[mf][1] = 0.f;
#pragma unroll
        for (int nt = 0; nt < 8; nt++)
#pragma unroll
            for (int q = 0; q < 4; q++) o[mf][nt][q] = 0.f;
    }

    for (int it = 0; it < 64; it++) {
        __syncthreads();   // previous tile's compute done (it=0: Q staged)
#pragma unroll
        for (int i = 0; i < 4; i++) {
            int s = i * 16 + kv_s;
            *(uint4*)&KS(s, kv_d) = make_uint4(f2tf(kr[i].x), f2tf(kr[i].y),
                                               f2tf(kr[i].z), f2tf(kr[i].w));
            *(uint4*)&VS(s, kv_d) = make_uint4(f2tf(vr[i].x), f2tf(vr[i].y),
                                               f2tf(vr[i].z), f2tf(vr[i].w));
        }
        __syncthreads();   // tile ready

        if (it + 1 < 64) {   // prefetch next tile (overlaps compute)
#pragma unroll
            for (int i = 0; i < 4; i++) {
                size_t ga = (size_t)((it + 1) * 64 + i * 16 + kv_s) * (NKV * DHEAD)
                            + kvh * DHEAD + kv_d;
                kr[i] = *(const float4*)(g_k + ga);
                vr[i] = *(const float4*)(g_v + ga);
            }
        }

        // S = Q @ K^T for both m-frags; K b-frags shared
        float sacc[2][8][4];
#pragma unroll
        for (int mf = 0; mf < 2; mf++)
#pragma unroll
            for (int nt = 0; nt < 8; nt++)
#pragma unroll
                for (int q = 0; q < 4; q++) sacc[mf][nt][q] = 0.f;

#pragma unroll
        for (int kc = 0; kc < 8; kc++) {
            uint32_t a[2][4];
#pragma unroll
            for (int mf = 0; mf < 2; mf++) {
                int rbm = rw + mf * 16 + g;
                a[mf][0] = QS(rbm, kc * 8 + t);
                a[mf][1] = QS(rbm + 8, kc * 8 + t);
                a[mf][2] = QS(rbm, kc * 8 + t + 4);
                a[mf][3] = QS(rbm + 8, kc * 8 + t + 4);
            }
#pragma unroll
            for (int nt = 0; nt < 8; nt++) {
                uint32_t b0 = KS(nt * 8 + g, kc * 8 + t);
                uint32_t b1 = KS(nt * 8 + g, kc * 8 + t + 4);
                mma_tf32(sacc[0][nt], a[0][0], a[0][1], a[0][2], a[0][3], b0, b1);
                mma_tf32(sacc[1][nt], a[1][0], a[1][1], a[1][2], a[1][3], b0, b1);
            }
        }

        // Online softmax per m-frag; overwrite sacc with tf32 bits of exp(S-m)
        float al[2][2];
#pragma unroll
        for (int mf = 0; mf < 2; mf++) {
            float mx0 = -1e30f, mx1 = -1e30f;
#pragma unroll
            for (int nt = 0; nt < 8; nt++) {
                mx0 = fmaxf(mx0, fmaxf(sacc[mf][nt][0], sacc[mf][nt][1]));
                mx1 = fmaxf(mx1, fmaxf(sacc[mf][nt][2], sacc[mf][nt][3]));
            }
            mx0 = fmaxf(mx0, __shfl_xor_sync(0xffffffffu, mx0, 1));
            mx0 = fmaxf(mx0, __shfl_xor_sync(0xffffffffu, mx0, 2));
            mx1 = fmaxf(mx1, __shfl_xor_sync(0xffffffffu, mx1, 1));
            mx1 = fmaxf(mx1, __shfl_xor_sync(0xffffffffu, mx1, 2));
            float mn0 = fmaxf(mr[mf][0], mx0), mn1 = fmaxf(mr[mf][1], mx1);
            al[mf][0] = __expf(mr[mf][0] - mn0);
            al[mf][1] = __expf(mr[mf][1] - mn1);
            mr[mf][0] = mn0; mr[mf][1] = mn1;

            float rs0 = 0.f, rs1 = 0.f;
#pragma unroll
            for (int nt = 0; nt < 8; nt++) {
                float p0 = __expf(sacc[mf][nt][0] - mn0);
                float p1 = __expf(sacc[mf][nt][1] - mn0);
                float p2 = __expf(sacc[mf][nt][2] - mn1);
                float p3 = __expf(sacc[mf][nt][3] - mn1);
                rs0 += p0 + p1; rs1 += p2 + p3;
                sacc[mf][nt][0] = __uint_as_float(f2tf(p0));
                sacc[mf][nt][1] = __uint_as_float(f2tf(p1));
                sacc[mf][nt][2] = __uint_as_float(f2tf(p2));
                sacc[mf][nt][3] = __uint_as_float(f2tf(p3));
            }
            rs0 += __shfl_xor_sync(0xffffffffu, rs0, 1);
            rs0 += __shfl_xor_sync(0xffffffffu, rs0, 2);
            rs1 += __shfl_xor_sync(0xffffffffu, rs1, 1);
            rs1 += __shfl_xor_sync(0xffffffffu, rs1, 2);
            l[mf][0] = l[mf][0] * al[mf][0] + rs0;
            l[mf][1] = l[mf][1] * al[mf][1] + rs1;
#pragma unroll
            for (int nt = 0; nt < 8; nt++) {
                o[mf][nt][0] *= al[mf][0]; o[mf][nt][1] *= al[mf][0];
                o[mf][nt][2] *= al[mf][1]; o[mf][nt][3] *= al[mf][1];
            }
        }

        // O += P @ V ; P A-frags from sacc C-layout via shuffles; V b shared
#pragma unroll
        for (int kc = 0; kc < 8; kc++) {
            uint32_t a[2][4];
#pragma unroll
            for (int mf = 0; mf < 2; mf++) {
                uint32_t p0 = __float_as_uint(sacc[mf][kc][0]);
                uint32_t p1 = __float_as_uint(sacc[mf][kc][1]);
                uint32_t p2 = __float_as_uint(sacc[mf][kc][2]);
                uint32_t p3 = __float_as_uint(sacc[mf][kc][3]);
                uint32_t sA0 = __shfl_sync(0xffffffffu, p0, srcA);
                uint32_t sA1 = __shfl_sync(0xffffffffu, p1, srcA);
                uint32_t sA2 = __shfl_sync(0xffffffffu, p2, srcA);
                uint32_t sA3 = __shfl_sync(0xffffffffu, p3, srcA);
                uint32_t sB0 = __shfl_sync(0xffffffffu, p0, srcB);
                uint32_t sB1 = __shfl_sync(0xffffffffu, p1, srcB);
                uint32_t sB2 = __shfl_sync(0xffffffffu, p2, srcB);
                uint32_t sB3 = __shfl_sync(0xffffffffu, p3, srcB);
                a[mf][0] = odd ? sA1 : sA0;
                a[mf][1] = odd ? sA3 : sA2;
                a[mf][2] = odd ? sB1 : sB0;
                a[mf][3] = odd ? sB3 : sB2;
            }
#pragma unroll
            for (int nt = 0; nt < 8; nt++) {
                uint32_t b0 = VS(kc * 8 + t, nt * 8 + g);
                uint32_t b1 = VS(kc * 8 + t + 4, nt * 8 + g);
                mma_tf32(o[0][nt], a[0][0], a[0][1], a[0][2], a[0][3], b0, b1);
                mma_tf32(o[1][nt], a[1][0], a[1][1], a[1][2], a[1][3], b0, b1);
            }
        }
    }

    // l already holds full row sums (quad-reduced every tile)
#pragma unroll
    for (int mf = 0; mf < 2; mf++) {
        float inv0 = 1.0f / l[mf][0], inv1 = 1.0f / l[mf][1];
        int row = q0 + rw + mf * 16 + g;
#pragma unroll
        for (int nt = 0; nt < 8; nt++) {
            int col = h * DHEAD + nt * 8 + 2 * t;
            *(float2*)(g_att + (size_t)row * (NH * DHEAD) + col) =
                make_float2(o[mf][nt][0] * inv0, o[mf][nt][1] * inv0);
            *(float2*)(g_att + (size_t)(row + 8) * (NH * DHEAD) + col) =
                make_float2(o[mf][nt][2] * inv1, o[mf][nt][3] * inv1);
        }
    }
}

// ---------------------------------------------------------------------------
extern "C" void kernel_launch(void* const* d_in, const int* in_sizes, int n_in,
                              void* d_out, int out_size) {
    const float* x  = (const float*)d_in[0];
    const float* Wq = (const float*)d_in[1];
    const float* Wk = (const float*)d_in[2];
    const float* Wv = (const float*)d_in[3];
    const float* Wo = (const float*)d_in[4];
    float* out = (float*)d_out;

    float *qp, *kp;
    cudaGetSymbolAddress((void**)&qp, g_q);
    cudaGetSymbolAddress((void**)&kp, g_k);

    cudaFuncSetAttribute(qkv_gemm,   cudaFuncAttributeMaxDynamicSharedMemorySize, GEMM_SMEM_BYTES);
    cudaFuncSetAttribute(oproj_gemm, cudaFuncAttributeMaxDynamicSharedMemorySize, GEMM_SMEM_BYTES);
    cudaFuncSetAttribute(attn_tf32,  cudaFuncAttributeMaxDynamicSharedMemorySize, ATT_SMEM_BYTES);

    qkv_gemm<<<dim3(12, 32), 256, GEMM_SMEM_BYTES>>>(x, Wq, Wk, Wv);
    rope<<<(LSEQ * NH * 32 + 255) / 256, 256>>>(qp, NH);
    rope<<<(LSEQ * NKV * 32 + 255) / 256, 256>>>(kp, NKV);
    attn_tf32<<<dim3(LSEQ / 256, NH), 256, ATT_SMEM_BYTES>>>();
    oproj_gemm<<<dim3(DMODEL / 128, LSEQ / 128), 256, GEMM_SMEM_BYTES>>>(Wo, out);
}